// round 4
// baseline (speedup 1.0000x reference)
#include <cuda_runtime.h>
#include <cuda_bf16.h>
#include <cstdint>

#define NNODES 50000
#define NEDGES 800000
#define NGRAPH 256
#define INC    128
#define HID    256

#define BM 128
#define BN 128
#define BK 32
#define SA 40    // A smem row stride (bf16 elems): BK + 8   (80B = 5*16 ✓)
#define SB 136   // B smem row stride: BN + 8                (272B = 17*16 ✓)
#define SMEM_BYTES ((4 * BM * SA + 4 * BK * SB) * 2)  // 75776

// Scratch (static device globals: allocation-free per harness rules)
static __device__ __align__(16) float g_z[(size_t)NNODES * HID];
static __device__ __align__(16) float g_t[(size_t)NNODES * HID];
static __device__ __align__(16) float g_h[(size_t)NNODES * HID];
static __device__ unsigned g_flags[2];

__device__ __forceinline__ int ld_idx(const void* p, long long i, bool is64) {
    if (is64) return (int)__ldg(&((const long long*)p)[i]);
    return __ldg(&((const int*)p)[i]);
}

// Pack 2 floats -> bf16x2 hi, and bf16x2 residual lo
__device__ __forceinline__ void cvt_hilo(float x0, float x1, unsigned& hi, unsigned& lo) {
    unsigned h;
    asm("cvt.rn.bf16x2.f32 %0, %1, %2;" : "=r"(h) : "f"(x1), "f"(x0));
    float f0 = __uint_as_float(h << 16);
    float f1 = __uint_as_float(h & 0xffff0000u);
    float r0 = x0 - f0, r1 = x1 - f1;
    unsigned l;
    asm("cvt.rn.bf16x2.f32 %0, %1, %2;" : "=r"(l) : "f"(r1), "f"(r0));
    hi = h; lo = l;
}

__global__ void k_init(float* __restrict__ out) {
    int tid = blockIdx.x * blockDim.x + threadIdx.x;
    if (tid < 2) g_flags[tid] = 0u;
    for (int i = tid; i < NGRAPH * HID; i += gridDim.x * blockDim.x) out[i] = 0.f;
}

__global__ void k_detect(const unsigned* __restrict__ ei, const unsigned* __restrict__ ba) {
    long long stride = (long long)gridDim.x * blockDim.x;
    long long tid = (long long)blockIdx.x * blockDim.x + threadIdx.x;
    unsigned acc = 0;
    for (long long w = 2 * tid + 1; w < 2LL * NEDGES; w += 2 * stride) acc |= ei[w];
    if (acc) atomicOr(&g_flags[0], 1u);
    acc = 0;
    for (long long w = 2 * tid + 1; w < NNODES; w += 2 * stride) acc |= ba[w];
    if (acc) atomicOr(&g_flags[1], 1u);
}

__global__ void k_copy4(const float4* __restrict__ src, float4* __restrict__ dst, long long n4) {
    long long stride = (long long)gridDim.x * blockDim.x;
    for (long long i = (long long)blockIdx.x * blockDim.x + threadIdx.x; i < n4; i += stride)
        dst[i] = src[i];
}

__global__ void k_scatter(const float* __restrict__ h, float* __restrict__ z,
                          const void* __restrict__ ei, int lg) {
    bool is64 = (g_flags[0] == 0u);
    long long total = (long long)NEDGES << lg;
    long long stride = (long long)gridDim.x * blockDim.x;
    long long mask = (1LL << lg) - 1;
    for (long long t = (long long)blockIdx.x * blockDim.x + threadIdx.x; t < total; t += stride) {
        long long e = t >> lg;
        int c = (int)(t & mask) * 4;
        int s = ld_idx(ei, e, is64);
        int d = ld_idx(ei, (long long)NEDGES + e, is64);
        const float4 v = *(const float4*)(h + ((long long)s << (lg + 2)) + c);
        float* dp = z + ((long long)d << (lg + 2)) + c;
        asm volatile("red.global.add.v4.f32 [%0], {%1,%2,%3,%4};"
                     :: "l"(dp), "f"(v.x), "f"(v.y), "f"(v.z), "f"(v.w) : "memory");
    }
}

// C = relu(A[M,K]@B[K,256] + bias) via bf16x3 split on tensor cores.
// Double-buffered smem + register prefetch pipeline. Optional second output C2.
__global__ void __launch_bounds__(256)
k_gemm_bf16x3(const float* __restrict__ A, const float* __restrict__ B,
              const float* __restrict__ bias, float* __restrict__ C,
              float* __restrict__ C2, int K) {
    extern __shared__ __align__(16) unsigned short sm[];
    unsigned short* AhB = sm;                    // [2][BM*SA]
    unsigned short* AlB = AhB + 2 * BM * SA;     // [2][BM*SA]
    unsigned short* BhB = AlB + 2 * BM * SA;     // [2][BK*SB]
    unsigned short* BlB = BhB + 2 * BK * SB;     // [2][BK*SB]

    const int M = NNODES;
    int tid = threadIdx.x;
    int lane = tid & 31, warp = tid >> 5;
    int wm = (warp & 1) * 64, wn = (warp >> 1) * 32;
    int row0 = blockIdx.x * BM, col0 = blockIdx.y * BN;

    float c[4][4][4];
#pragma unroll
    for (int mt = 0; mt < 4; mt++)
#pragma unroll
        for (int nt = 0; nt < 4; nt++)
#pragma unroll
            for (int i = 0; i < 4; i++) c[mt][nt][i] = 0.f;

    // Per-i staging indices
    int ar[4], aq[4], br[4], bq[4];
#pragma unroll
    for (int i = 0; i < 4; i++) {
        int lin = tid + i * 256;
        ar[i] = lin >> 3; aq[i] = lin & 7;
        br[i] = lin >> 5; bq[i] = lin & 31;
    }

    float4 pa[4], pb[4];

#define LOADT(KT)                                                                   \
    {                                                                               \
        _Pragma("unroll")                                                           \
        for (int i = 0; i < 4; i++) {                                               \
            int gr = row0 + ar[i];                                                  \
            pa[i] = make_float4(0.f, 0.f, 0.f, 0.f);                                \
            if (gr < M) pa[i] = *(const float4*)(A + (long long)gr * K + (KT) + aq[i] * 4); \
            pb[i] = *(const float4*)(B + (long long)((KT) + br[i]) * HID + col0 + bq[i] * 4); \
        }                                                                           \
    }

#define STORET(S)                                                                   \
    {                                                                               \
        unsigned short* Ah = AhB + (S) * BM * SA;                                   \
        unsigned short* Al = AlB + (S) * BM * SA;                                   \
        unsigned short* Bh = BhB + (S) * BK * SB;                                   \
        unsigned short* Bl = BlB + (S) * BK * SB;                                   \
        _Pragma("unroll")                                                           \
        for (int i = 0; i < 4; i++) {                                               \
            unsigned h0, l0, h1, l1;                                                \
            cvt_hilo(pa[i].x, pa[i].y, h0, l0);                                     \
            cvt_hilo(pa[i].z, pa[i].w, h1, l1);                                     \
            *(uint2*)&Ah[ar[i] * SA + aq[i] * 4] = make_uint2(h0, h1);              \
            *(uint2*)&Al[ar[i] * SA + aq[i] * 4] = make_uint2(l0, l1);              \
            cvt_hilo(pb[i].x, pb[i].y, h0, l0);                                     \
            cvt_hilo(pb[i].z, pb[i].w, h1, l1);                                     \
            *(uint2*)&Bh[br[i] * SB + bq[i] * 4] = make_uint2(h0, h1);              \
            *(uint2*)&Bl[br[i] * SB + bq[i] * 4] = make_uint2(l0, l1);              \
        }                                                                           \
    }

    int nkt = K / BK;
    LOADT(0);
    STORET(0);
    __syncthreads();

    for (int t = 0; t < nkt; t++) {
        int s = t & 1;
        if (t + 1 < nkt) LOADT((t + 1) * BK);

        // ---- compute on stage s ----
        const unsigned short* Ah = AhB + s * BM * SA;
        const unsigned short* Al = AlB + s * BM * SA;
        const unsigned short* Bh = BhB + s * BK * SB;
        const unsigned short* Bl = BlB + s * BK * SB;
#pragma unroll
        for (int kc = 0; kc < 2; kc++) {
            unsigned ah[4][4], al[4][4], bh[4][2], bl[4][2];
            int arow = lane & 15;
            int acol = kc * 16 + (lane >> 4) * 8;
#pragma unroll
            for (int mt = 0; mt < 4; mt++) {
                unsigned sa = (unsigned)__cvta_generic_to_shared(
                    &Ah[(wm + mt * 16 + arow) * SA + acol]);
                asm volatile("ldmatrix.sync.aligned.m8n8.x4.shared.b16 {%0,%1,%2,%3}, [%4];"
                             : "=r"(ah[mt][0]), "=r"(ah[mt][1]), "=r"(ah[mt][2]), "=r"(ah[mt][3])
                             : "r"(sa));
                unsigned sb = (unsigned)__cvta_generic_to_shared(
                    &Al[(wm + mt * 16 + arow) * SA + acol]);
                asm volatile("ldmatrix.sync.aligned.m8n8.x4.shared.b16 {%0,%1,%2,%3}, [%4];"
                             : "=r"(al[mt][0]), "=r"(al[mt][1]), "=r"(al[mt][2]), "=r"(al[mt][3])
                             : "r"(sb));
            }
            int brow = kc * 16 + (lane & 15);
#pragma unroll
            for (int nt2 = 0; nt2 < 2; nt2++) {
                int bcol = wn + nt2 * 16 + (lane >> 4) * 8;
                unsigned sh = (unsigned)__cvta_generic_to_shared(&Bh[brow * SB + bcol]);
                asm volatile("ldmatrix.sync.aligned.m8n8.x4.trans.shared.b16 {%0,%1,%2,%3}, [%4];"
                             : "=r"(bh[2 * nt2][0]), "=r"(bh[2 * nt2][1]),
                               "=r"(bh[2 * nt2 + 1][0]), "=r"(bh[2 * nt2 + 1][1])
                             : "r"(sh));
                unsigned sl = (unsigned)__cvta_generic_to_shared(&Bl[brow * SB + bcol]);
                asm volatile("ldmatrix.sync.aligned.m8n8.x4.trans.shared.b16 {%0,%1,%2,%3}, [%4];"
                             : "=r"(bl[2 * nt2][0]), "=r"(bl[2 * nt2][1]),
                               "=r"(bl[2 * nt2 + 1][0]), "=r"(bl[2 * nt2 + 1][1])
                             : "r"(sl));
            }
#pragma unroll
            for (int mt = 0; mt < 4; mt++)
#pragma unroll
                for (int nt = 0; nt < 4; nt++) {
                    float* cc = c[mt][nt];
#define MMA(AREG, BREG)                                                              \
    asm volatile("mma.sync.aligned.m16n8k16.row.col.f32.bf16.bf16.f32 "              \
                 "{%0,%1,%2,%3}, {%4,%5,%6,%7}, {%8,%9}, {%0,%1,%2,%3};"             \
                 : "+f"(cc[0]), "+f"(cc[1]), "+f"(cc[2]), "+f"(cc[3])                \
                 : "r"(AREG[0]), "r"(AREG[1]), "r"(AREG[2]), "r"(AREG[3]),           \
                   "r"(BREG[0]), "r"(BREG[1]))
                    MMA(ah[mt], bh[nt]);
                    MMA(ah[mt], bl[nt]);
                    MMA(al[mt], bh[nt]);
#undef MMA
                }
        }
        // ---- end compute ----

        if (t + 1 < nkt) STORET(s ^ 1);
        __syncthreads();
    }
#undef LOADT
#undef STORET

    // Epilogue: relu(c + bias), optional dual store
    int g = lane >> 2, tg = lane & 3;
#pragma unroll
    for (int nt = 0; nt < 4; nt++) {
        int gcol = col0 + wn + nt * 8 + tg * 2;
        float b0 = bias[gcol], b1 = bias[gcol + 1];
#pragma unroll
        for (int mt = 0; mt < 4; mt++) {
            int r0 = row0 + wm + mt * 16 + g;
            int r1 = r0 + 8;
            if (r0 < M) {
                float2 o;
                o.x = fmaxf(c[mt][nt][0] + b0, 0.f);
                o.y = fmaxf(c[mt][nt][1] + b1, 0.f);
                *(float2*)(C + (long long)r0 * HID + gcol) = o;
                if (C2) *(float2*)(C2 + (long long)r0 * HID + gcol) = o;
            }
            if (r1 < M) {
                float2 o;
                o.x = fmaxf(c[mt][nt][2] + b0, 0.f);
                o.y = fmaxf(c[mt][nt][3] + b1, 0.f);
                *(float2*)(C + (long long)r1 * HID + gcol) = o;
                if (C2) *(float2*)(C2 + (long long)r1 * HID + gcol) = o;
            }
        }
    }
}

__global__ void k_pool(const float* __restrict__ h, const void* __restrict__ ba,
                       float* __restrict__ out) {
    bool is64 = (g_flags[1] == 0u);
    long long total = (long long)NNODES * (HID / 4);
    long long stride = (long long)gridDim.x * blockDim.x;
    for (long long t = (long long)blockIdx.x * blockDim.x + threadIdx.x; t < total; t += stride) {
        long long i = t >> 6;
        int c = (int)(t & 63) * 4;
        int g = ld_idx(ba, i, is64);
        const float4 v = *(const float4*)(h + i * HID + c);
        float* dp = out + (long long)g * HID + c;
        asm volatile("red.global.add.v4.f32 [%0], {%1,%2,%3,%4};"
                     :: "l"(dp), "f"(v.x), "f"(v.y), "f"(v.z), "f"(v.w) : "memory");
    }
}

extern "C" void kernel_launch(void* const* d_in, const int* in_sizes, int n_in,
                              void* d_out, int out_size) {
    const float* x    = (const float*)d_in[0];
    const void*  ei   = d_in[1];
    const void*  ba   = d_in[2];
    const float* w1_0 = (const float*)d_in[3];
    const float* b1_0 = (const float*)d_in[4];
    const float* w2_0 = (const float*)d_in[5];
    const float* b2_0 = (const float*)d_in[6];
    const float* w1s  = (const float*)d_in[7];
    const float* b1s  = (const float*)d_in[8];
    const float* w2s  = (const float*)d_in[9];
    const float* b2s  = (const float*)d_in[10];
    float* out = (float*)d_out;

    float *z, *t, *h;
    cudaGetSymbolAddress((void**)&z, g_z);
    cudaGetSymbolAddress((void**)&t, g_t);
    cudaGetSymbolAddress((void**)&h, g_h);

    cudaFuncSetAttribute(k_gemm_bf16x3,
                         cudaFuncAttributeMaxDynamicSharedMemorySize, SMEM_BYTES);

    k_init<<<64, 256>>>(out);
    k_detect<<<256, 256>>>((const unsigned*)ei, (const unsigned*)ba);

    dim3 ggrid((NNODES + BM - 1) / BM, HID / BN);  // (391, 2)

    // Layer 0 (K = 128)
    k_copy4<<<2048, 256>>>((const float4*)x, (float4*)z, (long long)NNODES * INC / 4);
    k_scatter<<<4736, 256>>>(x, z, ei, 5);
    k_gemm_bf16x3<<<ggrid, 256, SMEM_BYTES>>>(z, w1_0, b1_0, t, nullptr, INC);
    k_gemm_bf16x3<<<ggrid, 256, SMEM_BYTES>>>(t, w2_0, b2_0, h, z, HID);  // z := h fused

    // Layers 1..3 (K = 256)
    for (int l = 0; l < 3; l++) {
        k_scatter<<<4736, 256>>>(h, z, ei, 6);
        k_gemm_bf16x3<<<ggrid, 256, SMEM_BYTES>>>(z, w1s + (long long)l * HID * HID,
                                                  b1s + l * HID, t, nullptr, HID);
        k_gemm_bf16x3<<<ggrid, 256, SMEM_BYTES>>>(t, w2s + (long long)l * HID * HID,
                                                  b2s + l * HID, h,
                                                  (l < 2) ? z : nullptr, HID);
    }

    k_pool<<<2048, 256>>>(h, ba, out);
}